// round 4
// baseline (speedup 1.0000x reference)
#include <cuda_runtime.h>

typedef unsigned long long u64;

// ---- packed f32x2 helpers (sm_103a packed fp32 pipe) ----
__device__ __forceinline__ u64 pk2(float l, float h) {
    u64 r; asm("mov.b64 %0, {%1,%2};" : "=l"(r) : "f"(l), "f"(h)); return r;
}
__device__ __forceinline__ u64 pkb(float w) { return pk2(w, w); }
__device__ __forceinline__ void upk(u64 v, float& l, float& h) {
    asm("mov.b64 {%0,%1}, %2;" : "=f"(l), "=f"(h) : "l"(v));
}
__device__ __forceinline__ u64 fma2(u64 a, u64 b, u64 c) {
    u64 d; asm("fma.rn.f32x2 %0, %1, %2, %3;" : "=l"(d) : "l"(a), "l"(b), "l"(c)); return d;
}
__device__ __forceinline__ u64 add2(u64 a, u64 b) {
    u64 d; asm("add.rn.f32x2 %0, %1, %2;" : "=l"(d) : "l"(a), "l"(b)); return d;
}
__device__ __forceinline__ u64 mul2(u64 a, u64 b) {
    u64 d; asm("mul.rn.f32x2 %0, %1, %2;" : "=l"(d) : "l"(a), "l"(b)); return d;
}

#define KDUP(bits) ((((u64)(bits)) << 32) | (u64)(bits))
static constexpr u64 K06   = KDUP(0x3F19999Au);  // 0.6f
static constexpr u64 K04   = KDUP(0x3ECCCCCDu);  // 0.4f
static constexpr u64 KABS  = 0x7FFFFFFF7FFFFFFFull;

// leaky_relu(x, 0.2) == 0.6*x + 0.4*|x|   (branch-free, fully packed)
__device__ __forceinline__ u64 leaky2(u64 v) {
    return fma2(v & KABS, K04, mul2(v, K06));
}

// HW tanh: 1 MUFU per scalar (vs 4 MUFU + ALU chain for exp-based)
__device__ __forceinline__ u64 tanh2(u64 v) {
    float l, h; upk(v, l, h);
    float tl, th;
    asm("tanh.approx.f32 %0, %1;" : "=f"(tl) : "f"(l));
    asm("tanh.approx.f32 %0, %1;" : "=f"(th) : "f"(h));
    return pk2(tl, th);
}

__global__ void __launch_bounds__(128, 4)
minigen_kernel(const float4* __restrict__ x,
               const float* __restrict__ w_enc1, const float* __restrict__ b_enc1,
               const float* __restrict__ w_bneck, const float* __restrict__ b_bneck,
               const float* __restrict__ w_dec1, const float* __restrict__ b_dec1,
               const float* __restrict__ w_out,  const float* __restrict__ b_out,
               float4* __restrict__ out)
{
    __shared__ float s_we[24], s_be[4];
    __shared__ float s_wb[96], s_bb[8];
    __shared__ float s_wdf[128], s_bd[4];   // dec1 folded: {w0, w2, w0+w1, w1+w2} per (c,ci)
    __shared__ float s_wof[32],  s_bo[2];   // out  folded

    int t = threadIdx.x;
    if (t < 24) s_we[t] = w_enc1[t];
    if (t < 96) s_wb[t] = w_bneck[t];
    if (t < 4)  { s_be[t] = b_enc1[t]; s_bd[t] = b_dec1[t]; }
    if (t < 8)  s_bb[t] = b_bneck[t];
    if (t < 2)  s_bo[t] = b_out[t];
    if (t < 32) {   // dec1 fold: t = c*8 + ci
        float w0 = w_dec1[t*3], w1 = w_dec1[t*3+1], w2 = w_dec1[t*3+2];
        s_wdf[t*4+0] = w0; s_wdf[t*4+1] = w2;
        s_wdf[t*4+2] = w0 + w1; s_wdf[t*4+3] = w1 + w2;
    }
    if (t < 8) {    // out fold: t = c*4 + ci
        float w0 = w_out[t*3], w1 = w_out[t*3+1], w2 = w_out[t*3+2];
        s_wof[t*4+0] = w0; s_wof[t*4+1] = w2;
        s_wof[t*4+2] = w0 + w1; s_wof[t*4+3] = w1 + w2;
    }
    __syncthreads();

    int i = blockIdx.x * blockDim.x + threadIdx.x;   // sample-pair index

    // ---- load 2 samples (2 x 128B contiguous lines), pack across samples ----
    u64 X2[32];
    {
        const float4* xp = x + (size_t)i * 16;
        float A[32], Bv[32];
        #pragma unroll
        for (int q = 0; q < 8; q++) {
            float4 va = xp[q];
            A[q*4+0] = va.x; A[q*4+1] = va.y; A[q*4+2] = va.z; A[q*4+3] = va.w;
        }
        #pragma unroll
        for (int q = 0; q < 8; q++) {
            float4 vb = xp[8 + q];
            Bv[q*4+0] = vb.x; Bv[q*4+1] = vb.y; Bv[q*4+2] = vb.z; Bv[q*4+3] = vb.w;
        }
        #pragma unroll
        for (int j = 0; j < 32; j++) X2[j] = pk2(A[j], Bv[j]);
    }

    // ---- enc1: conv(C2->C4, k3, s2, p1) + leaky -> E[4][8] ----
    u64 E[4][8];
    #pragma unroll
    for (int c = 0; c < 4; c++) {
        u64 w00 = pkb(s_we[c*6+0]), w01 = pkb(s_we[c*6+1]), w02 = pkb(s_we[c*6+2]);
        u64 w10 = pkb(s_we[c*6+3]), w11 = pkb(s_we[c*6+4]), w12 = pkb(s_we[c*6+5]);
        u64 b2 = pkb(s_be[c]);
        #pragma unroll
        for (int l = 0; l < 8; l++) {
            int p = 2 * l;
            u64 a = b2;
            if (l > 0) { a = fma2(w00, X2[p-1], a); a = fma2(w10, X2[16+p-1], a); }
            a = fma2(w01, X2[p],     a); a = fma2(w11, X2[16+p],   a);
            a = fma2(w02, X2[p+1],   a); a = fma2(w12, X2[16+p+1], a);
            E[c][l] = leaky2(a);
        }
    }
    // X2 dead past here.

    // ---- fused bneck + dec1: never materialize Bn[8][4] ----
    // dacc[c][l] accumulates the dec1 pre-activation.
    u64 dacc[4][8];
    #pragma unroll
    for (int c = 0; c < 4; c++) {
        u64 b2 = pkb(s_bd[c]);
        #pragma unroll
        for (int l = 0; l < 8; l++) dacc[c][l] = b2;
    }

    #pragma unroll
    for (int ci = 0; ci < 8; ci++) {
        // bneck channel ci: conv(C4, k3, s2, p1) + leaky -> bn[4]
        u64 bn[4];
        {
            u64 b2 = pkb(s_bb[ci]);
            #pragma unroll
            for (int l = 0; l < 4; l++) {
                int p = 2 * l;
                u64 a = b2;
                #pragma unroll
                for (int cc = 0; cc < 4; cc++) {
                    const float* wp = &s_wb[ci*12 + cc*3];
                    if (l > 0) a = fma2(pkb(wp[0]), E[cc][p-1], a);
                    a = fma2(pkb(wp[1]), E[cc][p],   a);
                    a = fma2(pkb(wp[2]), E[cc][p+1], a);
                }
                bn[l] = leaky2(a);
            }
        }
        // dec1 contribution of channel ci into all 4 output channels
        #pragma unroll
        for (int c = 0; c < 4; c++) {
            const float* wf = &s_wdf[(c*8 + ci) * 4];
            u64 w0 = pkb(wf[0]), w2 = pkb(wf[1]), w01 = pkb(wf[2]), w12 = pkb(wf[3]);
            dacc[c][0] = fma2(w12, bn[0], dacc[c][0]);
            dacc[c][1] = fma2(w01, bn[0], dacc[c][1]); dacc[c][1] = fma2(w2,  bn[1], dacc[c][1]);
            dacc[c][2] = fma2(w0,  bn[0], dacc[c][2]); dacc[c][2] = fma2(w12, bn[1], dacc[c][2]);
            dacc[c][3] = fma2(w01, bn[1], dacc[c][3]); dacc[c][3] = fma2(w2,  bn[2], dacc[c][3]);
            dacc[c][4] = fma2(w0,  bn[1], dacc[c][4]); dacc[c][4] = fma2(w12, bn[2], dacc[c][4]);
            dacc[c][5] = fma2(w01, bn[2], dacc[c][5]); dacc[c][5] = fma2(w2,  bn[3], dacc[c][5]);
            dacc[c][6] = fma2(w0,  bn[2], dacc[c][6]); dacc[c][6] = fma2(w12, bn[3], dacc[c][6]);
            dacc[c][7] = fma2(w01, bn[3], dacc[c][7]);
        }
    }

    // skip connection in place: E := leaky(dacc) + E   (this is S)
    #pragma unroll
    for (int c = 0; c < 4; c++)
        #pragma unroll
        for (int l = 0; l < 8; l++)
            E[c][l] = add2(leaky2(dacc[c][l]), E[c][l]);
    // dacc dead past here.

    // ---- out: upsample2 + conv(C4->C2, k3, s1, p1) + tanh; store per channel ----
    float4* op = out + (size_t)i * 16;
    #pragma unroll
    for (int c = 0; c < 2; c++) {
        u64 acc[16];
        u64 b2 = pkb(s_bo[c]);
        #pragma unroll
        for (int l = 0; l < 16; l++) acc[l] = b2;
        #pragma unroll
        for (int ci = 0; ci < 4; ci++) {
            const float* wf = &s_wof[(c*4 + ci) * 4];
            u64 w0 = pkb(wf[0]), w2 = pkb(wf[1]), w01 = pkb(wf[2]), w12 = pkb(wf[3]);
            acc[0]  = fma2(w12, E[ci][0], acc[0]);
            #pragma unroll
            for (int l = 1; l < 15; l++) {
                if ((l & 1) == 0) {
                    acc[l] = fma2(w0,  E[ci][l/2 - 1], acc[l]);
                    acc[l] = fma2(w12, E[ci][l/2],     acc[l]);
                } else {
                    acc[l] = fma2(w01, E[ci][(l-1)/2], acc[l]);
                    acc[l] = fma2(w2,  E[ci][(l+1)/2], acc[l]);
                }
            }
            acc[15] = fma2(w01, E[ci][7], acc[15]);
        }
        // tanh + immediate store of this channel's half-line for both samples
        #pragma unroll
        for (int q = 0; q < 4; q++) {
            u64 t0 = tanh2(acc[q*4+0]);
            u64 t1 = tanh2(acc[q*4+1]);
            u64 t2 = tanh2(acc[q*4+2]);
            u64 t3 = tanh2(acc[q*4+3]);
            float4 va, vb;
            upk(t0, va.x, vb.x); upk(t1, va.y, vb.y);
            upk(t2, va.z, vb.z); upk(t3, va.w, vb.w);
            op[c*4 + q]     = va;   // sample A, channel-c quarter q
            op[8 + c*4 + q] = vb;   // sample B
        }
    }
}

extern "C" void kernel_launch(void* const* d_in, const int* in_sizes, int n_in,
                              void* d_out, int out_size) {
    const float4* x      = (const float4*)d_in[0];
    const float* w_enc1  = (const float*)d_in[1];
    const float* b_enc1  = (const float*)d_in[2];
    const float* w_bneck = (const float*)d_in[3];
    const float* b_bneck = (const float*)d_in[4];
    const float* w_dec1  = (const float*)d_in[5];
    const float* b_dec1  = (const float*)d_in[6];
    const float* w_out   = (const float*)d_in[7];
    const float* b_out   = (const float*)d_in[8];
    float4* out = (float4*)d_out;

    int B = in_sizes[0] / 32;        // samples
    int pairs = B / 2;               // two samples per thread
    int threads = 128;
    int blocks = (pairs + threads - 1) / threads;
    minigen_kernel<<<blocks, threads>>>(x, w_enc1, b_enc1, w_bneck, b_bneck,
                                        w_dec1, b_dec1, w_out, b_out, out);
}

// round 7
// speedup vs baseline: 1.1156x; 1.1156x over previous
#include <cuda_runtime.h>

typedef unsigned long long u64;

// ---- packed f32x2 helpers (sm_103a packed fp32 pipe) ----
__device__ __forceinline__ u64 pk2(float l, float h) {
    u64 r; asm("mov.b64 %0, {%1,%2};" : "=l"(r) : "f"(l), "f"(h)); return r;
}
__device__ __forceinline__ u64 pkb(float w) { return pk2(w, w); }
__device__ __forceinline__ void upk(u64 v, float& l, float& h) {
    asm("mov.b64 {%0,%1}, %2;" : "=f"(l), "=f"(h) : "l"(v));
}
__device__ __forceinline__ u64 fma2(u64 a, u64 b, u64 c) {
    u64 d; asm("fma.rn.f32x2 %0, %1, %2, %3;" : "=l"(d) : "l"(a), "l"(b), "l"(c)); return d;
}
__device__ __forceinline__ u64 add2(u64 a, u64 b) {
    u64 d; asm("add.rn.f32x2 %0, %1, %2;" : "=l"(d) : "l"(a), "l"(b)); return d;
}
__device__ __forceinline__ u64 mul2(u64 a, u64 b) {
    u64 d; asm("mul.rn.f32x2 %0, %1, %2;" : "=l"(d) : "l"(a), "l"(b)); return d;
}

#define KDUP(bits) ((((u64)(bits)) << 32) | (u64)(bits))
static constexpr u64 K06  = KDUP(0x3F19999Au);  // 0.6f
static constexpr u64 K04  = KDUP(0x3ECCCCCDu);  // 0.4f
static constexpr u64 KABS = 0x7FFFFFFF7FFFFFFFull;

// leaky_relu(x, 0.2) == 0.6*x + 0.4*|x|   (branch-free, fully packed)
__device__ __forceinline__ u64 leaky2(u64 v) {
    return fma2(v & KABS, K04, mul2(v, K06));
}

// HW tanh: 1 MUFU per scalar
__device__ __forceinline__ u64 tanh2(u64 v) {
    float l, h; upk(v, l, h);
    float tl, th;
    asm("tanh.approx.f32 %0, %1;" : "=f"(tl) : "f"(l));
    asm("tanh.approx.f32 %0, %1;" : "=f"(th) : "f"(h));
    return pk2(tl, th);
}

__global__ void __launch_bounds__(128)
minigen_kernel(const float4* __restrict__ x,
               const float* __restrict__ w_enc1, const float* __restrict__ b_enc1,
               const float* __restrict__ w_bneck, const float* __restrict__ b_bneck,
               const float* __restrict__ w_dec1, const float* __restrict__ b_dec1,
               const float* __restrict__ w_out,  const float* __restrict__ b_out,
               float4* __restrict__ out)
{
    // all weights stored PRE-DUPLICATED as u64 -> inner loops do single LDS.64
    __shared__ u64 s_we[24], s_be[4];
    __shared__ u64 s_wb[96], s_bb[8];
    __shared__ u64 s_wdf[128], s_bd[4];   // dec1 folded: {w0, w2, w0+w1, w1+w2} per (c,ci)
    __shared__ u64 s_wof[32],  s_bo[2];   // out  folded

    int t = threadIdx.x;
    if (t < 24) s_we[t] = pkb(w_enc1[t]);
    if (t < 96) s_wb[t] = pkb(w_bneck[t]);
    if (t < 4)  { s_be[t] = pkb(b_enc1[t]); s_bd[t] = pkb(b_dec1[t]); }
    if (t < 8)  s_bb[t] = pkb(b_bneck[t]);
    if (t < 2)  s_bo[t] = pkb(b_out[t]);
    if (t < 32) {   // dec1 fold: t = c*8 + ci
        float w0 = w_dec1[t*3], w1 = w_dec1[t*3+1], w2 = w_dec1[t*3+2];
        s_wdf[t*4+0] = pkb(w0);      s_wdf[t*4+1] = pkb(w2);
        s_wdf[t*4+2] = pkb(w0 + w1); s_wdf[t*4+3] = pkb(w1 + w2);
    }
    if (t < 8) {    // out fold: t = c*4 + ci
        float w0 = w_out[t*3], w1 = w_out[t*3+1], w2 = w_out[t*3+2];
        s_wof[t*4+0] = pkb(w0);      s_wof[t*4+1] = pkb(w2);
        s_wof[t*4+2] = pkb(w0 + w1); s_wof[t*4+3] = pkb(w1 + w2);
    }
    __syncthreads();

    int i = blockIdx.x * blockDim.x + threadIdx.x;   // sample-pair index

    // ---- load 2 samples (2 x 128B contiguous lines), pack across samples ----
    u64 X2[32];
    {
        const float4* xp = x + (size_t)i * 16;
        float A[32], Bv[32];
        #pragma unroll
        for (int q = 0; q < 8; q++) {
            float4 va = xp[q];
            A[q*4+0] = va.x; A[q*4+1] = va.y; A[q*4+2] = va.z; A[q*4+3] = va.w;
        }
        #pragma unroll
        for (int q = 0; q < 8; q++) {
            float4 vb = xp[8 + q];
            Bv[q*4+0] = vb.x; Bv[q*4+1] = vb.y; Bv[q*4+2] = vb.z; Bv[q*4+3] = vb.w;
        }
        #pragma unroll
        for (int j = 0; j < 32; j++) X2[j] = pk2(A[j], Bv[j]);
    }

    // ---- enc1: conv(C2->C4, k3, s2, p1) + leaky -> E[4][8] ----
    u64 E[4][8];
    #pragma unroll
    for (int c = 0; c < 4; c++) {
        u64 w00 = s_we[c*6+0], w01 = s_we[c*6+1], w02 = s_we[c*6+2];
        u64 w10 = s_we[c*6+3], w11 = s_we[c*6+4], w12 = s_we[c*6+5];
        u64 b2 = s_be[c];
        #pragma unroll
        for (int l = 0; l < 8; l++) {
            int p = 2 * l;
            u64 a = b2;
            if (l > 0) { a = fma2(w00, X2[p-1], a); a = fma2(w10, X2[16+p-1], a); }
            a = fma2(w01, X2[p],     a); a = fma2(w11, X2[16+p],   a);
            a = fma2(w02, X2[p+1],   a); a = fma2(w12, X2[16+p+1], a);
            E[c][l] = leaky2(a);
        }
    }
    // X2 dead past here.

    // ---- bneck: conv(C4->C8, k3, s2, p1) + leaky -> Bn[8][4] ----
    u64 Bn[8][4];
    #pragma unroll
    for (int co = 0; co < 8; co++) {
        u64 wk[12];
        #pragma unroll
        for (int j = 0; j < 12; j++) wk[j] = s_wb[co*12 + j];
        u64 b2 = s_bb[co];
        #pragma unroll
        for (int l = 0; l < 4; l++) {
            int p = 2 * l;
            u64 a = b2;
            #pragma unroll
            for (int ci = 0; ci < 4; ci++) {
                if (l > 0) a = fma2(wk[ci*3+0], E[ci][p-1], a);
                a = fma2(wk[ci*3+1], E[ci][p],   a);
                a = fma2(wk[ci*3+2], E[ci][p+1], a);
            }
            Bn[co][l] = leaky2(a);
        }
    }

    // ---- dec1: upsample2 + conv(C8->C4, k3, s1, p1) + leaky, skip in-place into E
    #pragma unroll
    for (int c = 0; c < 4; c++) {
        u64 acc[8];
        u64 b2 = s_bd[c];
        #pragma unroll
        for (int l = 0; l < 8; l++) acc[l] = b2;
        #pragma unroll
        for (int ci = 0; ci < 8; ci++) {
            const u64* wf = &s_wdf[(c*8 + ci) * 4];
            u64 w0 = wf[0], w2 = wf[1], w01 = wf[2], w12 = wf[3];
            u64 q0 = Bn[ci][0], q1 = Bn[ci][1], q2 = Bn[ci][2], q3 = Bn[ci][3];
            acc[0] = fma2(w12, q0, acc[0]);
            acc[1] = fma2(w01, q0, acc[1]); acc[1] = fma2(w2,  q1, acc[1]);
            acc[2] = fma2(w0,  q0, acc[2]); acc[2] = fma2(w12, q1, acc[2]);
            acc[3] = fma2(w01, q1, acc[3]); acc[3] = fma2(w2,  q2, acc[3]);
            acc[4] = fma2(w0,  q1, acc[4]); acc[4] = fma2(w12, q2, acc[4]);
            acc[5] = fma2(w01, q2, acc[5]); acc[5] = fma2(w2,  q3, acc[5]);
            acc[6] = fma2(w0,  q2, acc[6]); acc[6] = fma2(w12, q3, acc[6]);
            acc[7] = fma2(w01, q3, acc[7]);
        }
        #pragma unroll
        for (int l = 0; l < 8; l++)
            E[c][l] = add2(leaky2(acc[l]), E[c][l]);   // skip connection -> S
    }
    // Bn dead past here.

    // ---- out: upsample2 + conv(C4->C2, k3, s1, p1) + tanh; store per channel ----
    float4* op = out + (size_t)i * 16;
    #pragma unroll
    for (int c = 0; c < 2; c++) {
        u64 acc[16];
        u64 b2 = s_bo[c];
        #pragma unroll
        for (int l = 0; l < 16; l++) acc[l] = b2;
        #pragma unroll
        for (int ci = 0; ci < 4; ci++) {
            const u64* wf = &s_wof[(c*4 + ci) * 4];
            u64 w0 = wf[0], w2 = wf[1], w01 = wf[2], w12 = wf[3];
            acc[0]  = fma2(w12, E[ci][0], acc[0]);
            #pragma unroll
            for (int l = 1; l < 15; l++) {
                if ((l & 1) == 0) {
                    acc[l] = fma2(w0,  E[ci][l/2 - 1], acc[l]);
                    acc[l] = fma2(w12, E[ci][l/2],     acc[l]);
                } else {
                    acc[l] = fma2(w01, E[ci][(l-1)/2], acc[l]);
                    acc[l] = fma2(w2,  E[ci][(l+1)/2], acc[l]);
                }
            }
            acc[15] = fma2(w01, E[ci][7], acc[15]);
        }
        #pragma unroll
        for (int q = 0; q < 4; q++) {
            u64 t0 = tanh2(acc[q*4+0]);
            u64 t1 = tanh2(acc[q*4+1]);
            u64 t2 = tanh2(acc[q*4+2]);
            u64 t3 = tanh2(acc[q*4+3]);
            float4 va, vb;
            upk(t0, va.x, vb.x); upk(t1, va.y, vb.y);
            upk(t2, va.z, vb.z); upk(t3, va.w, vb.w);
            op[c*4 + q]     = va;   // sample A, channel-c quarter q
            op[8 + c*4 + q] = vb;   // sample B
        }
    }
}

extern "C" void kernel_launch(void* const* d_in, const int* in_sizes, int n_in,
                              void* d_out, int out_size) {
    const float4* x      = (const float4*)d_in[0];
    const float* w_enc1  = (const float*)d_in[1];
    const float* b_enc1  = (const float*)d_in[2];
    const float* w_bneck = (const float*)d_in[3];
    const float* b_bneck = (const float*)d_in[4];
    const float* w_dec1  = (const float*)d_in[5];
    const float* b_dec1  = (const float*)d_in[6];
    const float* w_out   = (const float*)d_in[7];
    const float* b_out   = (const float*)d_in[8];
    float4* out = (float4*)d_out;

    int B = in_sizes[0] / 32;        // samples
    int pairs = B / 2;               // two samples per thread
    int threads = 128;
    int blocks = (pairs + threads - 1) / threads;
    minigen_kernel<<<blocks, threads>>>(x, w_enc1, b_enc1, w_bneck, b_bneck,
                                        w_dec1, b_dec1, w_out, b_out, out);
}